// round 16
// baseline (speedup 1.0000x reference)
#include <cuda_runtime.h>
#include <cuda_fp16.h>
#include <math.h>

#define B_  2
#define S_  2048
#define D_  2048
#define H_  16
#define HD_ 128
#define M_  (B_*S_)          // 4096

#define SCALE_ 0.08838834764831845f   // 1/sqrt(128)

// -------- scratch (fp16, 16B-aligned via uint4 backing) --------
static __device__ uint4 g_qh_raw [B_*H_*S_*HD_/8];
static __device__ uint4 g_kh_raw [B_*H_*S_*HD_/8];
static __device__ uint4 g_vh_raw [B_*H_*S_*HD_/8];
static __device__ uint4 g_aoh_raw[B_*S_*D_/8];
static __device__ uint4 g_xh_raw [B_*S_*D_/8];
static __device__ uint4 g_wq_raw [D_*D_/8];
static __device__ uint4 g_wk_raw [D_*D_/8];
static __device__ uint4 g_wv_raw [D_*D_/8];
static __device__ uint4 g_wo_raw [D_*D_/8];
// device-side accessors ONLY (never touch these from host code!)
#define g_qh  ((__half*)g_qh_raw)
#define g_kh  ((__half*)g_kh_raw)
#define g_vh  ((__half*)g_vh_raw)
#define g_aoh ((__half*)g_aoh_raw)
#define g_xh  ((__half*)g_xh_raw)
#define g_wq  ((__half*)g_wq_raw)
#define g_wk  ((__half*)g_wk_raw)
#define g_wv  ((__half*)g_wv_raw)
#define g_wo  ((__half*)g_wo_raw)

// ===================== helpers =========================
__device__ __forceinline__ unsigned smem_u32(const void* p) {
    unsigned a;
    asm("{ .reg .u64 t; cvta.to.shared.u64 t, %1; cvt.u32.u64 %0, t; }"
        : "=r"(a) : "l"(p));
    return a;
}

#define LDSM4(r0,r1,r2,r3,a) \
    asm volatile("ldmatrix.sync.aligned.m8n8.x4.shared.b16 {%0,%1,%2,%3}, [%4];" \
        : "=r"(r0),"=r"(r1),"=r"(r2),"=r"(r3) : "r"(a))

#define MMAF16(d, a0,a1,a2,a3, b0,b1) \
    asm volatile("mma.sync.aligned.m16n8k16.row.col.f32.f16.f16.f32 " \
        "{%0,%1,%2,%3}, {%4,%5,%6,%7}, {%8,%9}, {%0,%1,%2,%3};" \
        : "+f"((d)[0]),"+f"((d)[1]),"+f"((d)[2]),"+f"((d)[3]) \
        : "r"(a0),"r"(a1),"r"(a2),"r"(a3),"r"(b0),"r"(b1))

#define CP16(dst, src) \
    asm volatile("cp.async.cg.shared.global [%0], [%1], 16;" \
                 :: "r"(dst), "l"(src) : "memory")
#define CP_COMMIT() asm volatile("cp.async.commit_group;" ::: "memory")
#define CP_WAIT0()  asm volatile("cp.async.wait_group 0;"  ::: "memory")
#define CP_WAIT1()  asm volatile("cp.async.wait_group 1;"  ::: "memory")

// pack two fp32 -> half2 (lo = first arg)
__device__ __forceinline__ unsigned h2pack(float lo, float hi) {
    unsigned r;
    asm("cvt.rn.f16x2.f32 %0, %1, %2;" : "=r"(r) : "f"(hi), "f"(lo));
    return r;
}
__device__ __forceinline__ float2 h2unpack(unsigned u) {
    __half2 h = *(__half2*)&u;
    return __half22float2(h);
}

// =====================================================================
// Single fused fp32 -> fp16 convert for x + 4 weights.
// Flat grid: blocks [0,4096): x ; [4096,12288): weights (2048 each).
// =====================================================================
__global__ void f2h_all(const float* __restrict__ x,
                        const float* __restrict__ wq,
                        const float* __restrict__ wk,
                        const float* __restrict__ wv,
                        const float* __restrict__ wo)
{
    int b = blockIdx.x;
    const float* src;
    __half* dst;
    int off;
    if (b < 4096) {
        src = x; dst = g_xh; off = b;
    } else {
        int w = (b - 4096) >> 11;        // 0..3
        off = (b - 4096) & 2047;
        src = (w == 0) ? wq : (w == 1) ? wk : (w == 2) ? wv : wo;
        dst = (w == 0) ? g_wq : (w == 1) ? g_wk : (w == 2) ? g_wv : g_wo;
    }
    int i = off * 2048 + threadIdx.x * 8;
    float4 a = *(const float4*)(src + i);
    float4 c = *(const float4*)(src + i + 4);
    uint4 r;
    r.x = h2pack(a.x, a.y); r.y = h2pack(a.z, a.w);
    r.z = h2pack(c.x, c.y); r.w = h2pack(c.z, c.w);
    *(uint4*)(dst + i) = r;
}

// =====================================================================
// fp16 NT GEMM (fp32 accum): C[m,n] = sum_k A[m,k] * W[n,k].
// CTA tile 128x128, warp tile 32x64 (4x2 grid), BK=32, 256 threads,
// cp.async.cg 16B staging, 3-stage pipeline (61.4KB), 2 CTA/SM.
// mode=0 (QKV): A=g_xh, W per blockIdx.z, scatter fp16 [B,H,S,HD]
// mode=1 (out): A=g_aoh, W=g_wo, write fp32 row-major to Cout
// (R14-validated: separate rope kernel, plain scatter epilogue)
// =====================================================================
#define TM 128
#define TN 128
#define BKH 32
#define GNCH (D_/BKH)         // 64
#define HRS 40                // halves per row (80B; 16B-aligned rows)
#define ASZ (TM*HRS*2)        // 10240 B
#define BSZ (TN*HRS*2)        // 10240 B
#define BUF (ASZ+BSZ)         // 20480
#define NSTG 3
#define GS  (NSTG*BUF)        // 61440

__global__ __launch_bounds__(256, 2) void gemm_h(float* __restrict__ Cout, int mode)
{
    extern __shared__ char sm_[];
    const unsigned sbase = smem_u32(sm_);

    const int tid = threadIdx.x;
    const int wid = tid >> 5, lid = tid & 31;
    const int m0 = blockIdx.y * TM;
    const int n0 = blockIdx.x * TN;

    const __half* A;
    const __half* W;
    __half* outh = nullptr;
    if (mode == 0) {
        A = g_xh;
        W    = (blockIdx.z == 0) ? g_wq : (blockIdx.z == 1) ? g_wk : g_wv;
        outh = (blockIdx.z == 0) ? g_qh : (blockIdx.z == 1) ? g_kh : g_vh;
    } else {
        A = g_aoh;
        W = g_wo;
    }

    const int wm = wid >> 1, wn = wid & 1;   // warp tile rows wm*32, cols wn*64

    const unsigned aoff0 = (unsigned)(((wm*32 + (lid & 7) + ((lid & 8) ? 8 : 0)) * HRS
                                       + ((lid & 16) ? 8 : 0)) * 2);
    const unsigned boff0 = (unsigned)(((wn*64 + (lid & 7) + ((lid & 16) ? 8 : 0)) * HRS
                                       + ((lid & 8) ? 8 : 0)) * 2);

    // cp.async staging: rows tid>>2 and +64, 16B seg tid&3 (seg*8 halves)
    const int srow = tid >> 2, sseg = tid & 3;

    float acc[2][8][4];
#pragma unroll
    for (int mt = 0; mt < 2; mt++)
#pragma unroll
        for (int nt = 0; nt < 8; nt++)
#pragma unroll
            for (int e = 0; e < 4; e++) acc[mt][nt][e] = 0.f;

    // ---- prologue: async-load chunks 0 and 1 ----
#pragma unroll
    for (int pc = 0; pc < 2; pc++) {
        unsigned d = sbase + (unsigned)pc * BUF;
        int k0 = pc * BKH;
#pragma unroll
        for (int i = 0; i < 2; i++) {
            int r = srow + i*64;
            CP16(d + (unsigned)((r*HRS + sseg*8)*2),
                 A + (size_t)(m0 + r) * D_ + k0 + sseg*8);
            CP16(d + ASZ + (unsigned)((r*HRS + sseg*8)*2),
                 W + (size_t)(n0 + r) * D_ + k0 + sseg*8);
        }
        CP_COMMIT();
    }
    CP_WAIT1();       // chunk 0 resident
    __syncthreads();

#pragma unroll 1
    for (int c = 0; c < GNCH; c++) {
        // issue async copies for chunk c+2 (keep 2 chunks in flight)
        const int ci2 = c + 2;
        if (ci2 < GNCH) {
            unsigned d = sbase + (unsigned)(ci2 % NSTG) * BUF;
            int k0 = ci2 * BKH;
#pragma unroll
            for (int i = 0; i < 2; i++) {
                int r = srow + i*64;
                CP16(d + (unsigned)((r*HRS + sseg*8)*2),
                     A + (size_t)(m0 + r) * D_ + k0 + sseg*8);
                CP16(d + ASZ + (unsigned)((r*HRS + sseg*8)*2),
                     W + (size_t)(n0 + r) * D_ + k0 + sseg*8);
            }
            CP_COMMIT();
        }

        // ---- MMA over chunk c: 2 k16-steps ----
        const unsigned sA = sbase + (unsigned)(c % NSTG) * BUF;
        const unsigned sB = sA + ASZ;
#pragma unroll
        for (int ks = 0; ks < 2; ks++) {
            const unsigned kso = (unsigned)(ks * 32);   // 16 halves
            unsigned a0[2], a1[2], a2[2], a3[2];
#pragma unroll
            for (int mt = 0; mt < 2; mt++)
                LDSM4(a0[mt], a1[mt], a2[mt], a3[mt],
                      sA + aoff0 + (unsigned)(mt*16*HRS*2) + kso);
#pragma unroll
            for (int p = 0; p < 4; p++) {
                unsigned b0, b1, b2, b3;
                LDSM4(b0, b1, b2, b3,
                      sB + boff0 + (unsigned)(p*16*HRS*2) + kso);
#pragma unroll
                for (int mt = 0; mt < 2; mt++) {
                    MMAF16(acc[mt][2*p],   a0[mt], a1[mt], a2[mt], a3[mt], b0, b1);
                    MMAF16(acc[mt][2*p+1], a0[mt], a1[mt], a2[mt], a3[mt], b2, b3);
                }
            }
        }

        // ensure chunk c+1 is resident before next iteration
        if (ci2 < GNCH)            CP_WAIT1();
        else if (c + 1 < GNCH)     CP_WAIT0();
        __syncthreads();
    }

    // ---- epilogue (c-frag: rows lid>>2 / +8, cols (lid&3)*2) ----
#pragma unroll
    for (int mt = 0; mt < 2; mt++)
#pragma unroll
    for (int nt = 0; nt < 8; nt++) {
        int r  = m0 + wm*32 + mt*16 + (lid >> 2);
        int cc = n0 + wn*64 + nt*8 + (lid & 3)*2;
        if (mode != 0) {
            *(float2*)(Cout + (size_t)r * D_ + cc) =
                make_float2(acc[mt][nt][0], acc[mt][nt][1]);
            *(float2*)(Cout + (size_t)(r + 8) * D_ + cc) =
                make_float2(acc[mt][nt][2], acc[mt][nt][3]);
        } else {
            int h = cc >> 7, cd = cc & 127;
            int b1 = r >> 11, s1 = r & (S_ - 1);
            *(unsigned*)(outh + ((size_t)(b1*H_ + h) * S_ + s1) * HD_ + cd) =
                h2pack(acc[mt][nt][0], acc[mt][nt][1]);
            int r2 = r + 8;
            int b2 = r2 >> 11, s2 = r2 & (S_ - 1);
            *(unsigned*)(outh + ((size_t)(b2*H_ + h) * S_ + s2) * HD_ + cd) =
                h2pack(acc[mt][nt][2], acc[mt][nt][3]);
        }
    }
}

// =====================================================================
// RoPE in-place on fp16 g_qh, g_kh (compute fp32, 4 d-values / thread).
// =====================================================================
__global__ void rope_h(const float* __restrict__ cosT,
                       const float* __restrict__ sinT)
{
    int idx = blockIdx.x * blockDim.x + threadIdx.x;   // over B*H*S*16
    int d4 = (idx & 15) << 2;
    int s  = (idx >> 4) & (S_ - 1);
    int bh = idx >> 15;
    size_t base = ((size_t)bh * S_ + s) * HD_;
    float4 c  = *(const float4*)&cosT[s*HD_ + d4];
    float4 sn = *(const float4*)&sinT[s*HD_ + d4];

    uint2 q1u = *(uint2*)(g_qh + base + d4);
    uint2 q2u = *(uint2*)(g_qh + base + d4 + 64);
    float2 q1a = h2unpack(q1u.x), q1b = h2unpack(q1u.y);
    float2 q2a = h2unpack(q2u.x), q2b = h2unpack(q2u.y);
    uint2 o1, o2;
    o1.x = h2pack(q1a.x*c.x - q2a.x*sn.x, q1a.y*c.y - q2a.y*sn.y);
    o1.y = h2pack(q1b.x*c.z - q2b.x*sn.z, q1b.y*c.w - q2b.y*sn.w);
    o2.x = h2pack(q2a.x*c.x + q1a.x*sn.x, q2a.y*c.y + q1a.y*sn.y);
    o2.y = h2pack(q2b.x*c.z + q1b.x*sn.z, q2b.y*c.w + q1b.y*sn.w);
    *(uint2*)(g_qh + base + d4)      = o1;
    *(uint2*)(g_qh + base + d4 + 64) = o2;

    uint2 k1u = *(uint2*)(g_kh + base + d4);
    uint2 k2u = *(uint2*)(g_kh + base + d4 + 64);
    float2 k1a = h2unpack(k1u.x), k1b = h2unpack(k1u.y);
    float2 k2a = h2unpack(k2u.x), k2b = h2unpack(k2u.y);
    o1.x = h2pack(k1a.x*c.x - k2a.x*sn.x, k1a.y*c.y - k2a.y*sn.y);
    o1.y = h2pack(k1b.x*c.z - k2b.x*sn.z, k1b.y*c.w - k2b.y*sn.w);
    o2.x = h2pack(k2a.x*c.x + k1a.x*sn.x, k2a.y*c.y + k1a.y*sn.y);
    o2.y = h2pack(k2b.x*c.z + k1b.x*sn.z, k2b.y*c.w + k1b.y*sn.w);
    *(uint2*)(g_kh + base + d4)      = o1;
    *(uint2*)(g_kh + base + d4 + 64) = o2;
}

// =====================================================================
// Flash attention on fp16 tensor cores (fp32 accum). BQ=128, BK=64,
// 8 warps, P in registers. NOW 2 CTA/SM (141KB smem total) so one
// CTA's MMA hides the other's softmax/staging phases.
// =====================================================================
#define QH 136
#define VH 72
#define KS_OFFH (128*QH)
#define VT_OFFH (KS_OFFH + 64*QH)
#define ATT3_SMEM ((VT_OFFH + 128*VH) * 2)   // 70656 bytes

__global__ __launch_bounds__(256, 2) void attn_h()
{
    extern __shared__ __half hsm[];
    __half* Qs = hsm;
    __half* Ks = hsm + KS_OFFH;
    __half* VT = hsm + VT_OFFH;

    const int tid = threadIdx.x;
    const int wid = tid >> 5, lid = tid & 31;
    const int qb  = 15 - (int)blockIdx.x;
    const int bh  = blockIdx.y;
    const int q0  = qb * 128;

    const __half* qph = g_qh + (size_t)bh * S_ * HD_;
    const __half* kph = g_kh + (size_t)bh * S_ * HD_;
    const __half* vph = g_vh + (size_t)bh * S_ * HD_;

    // ---- load Q tile (direct fp16 copy, 16B segs) ----
#pragma unroll
    for (int i = 0; i < 8; i++) {
        int pos = i*256 + tid;            // 2048 segs
        int row = pos >> 4;
        int seg = pos & 15;
        *(uint4*)(Qs + row*QH + seg*8) =
            *(const uint4*)(qph + (size_t)(q0 + row) * HD_ + seg*8);
    }

    const int a_ = lid >> 2, q_ = lid & 3;
    const int r0g = q0 + wid*16 + a_;

    const unsigned aq_base = smem_u32(Qs) +
        (unsigned)(((wid*16 + (lid & 7) + ((lid & 8) ? 8 : 0)) * QH
                    + ((lid & 16) ? 8 : 0)) * 2);
    const unsigned ks_lane = smem_u32(Ks) +
        (unsigned)((((lid & 7) + ((lid & 16) ? 8 : 0)) * QH
                    + ((lid & 8) ? 8 : 0)) * 2);
    const unsigned vt_lane = smem_u32(VT) +
        (unsigned)((((lid & 7) + ((lid & 16) ? 8 : 0)) * VH
                    + ((lid & 8) ? 8 : 0)) * 2);

    float m0 = -INFINITY, m1 = -INFINITY, l0 = 0.f, l1 = 0.f;
    float o[16][4];
#pragma unroll
    for (int f = 0; f < 16; f++)
#pragma unroll
        for (int e = 0; e < 4; e++) o[f][e] = 0.f;

    const int nt = 2*qb + 2;
#pragma unroll 1
    for (int t = 0; t < nt; t++) {
        const int kb = t * 64;
        __syncthreads();
        // ---- stage K (row-major) and V (transposed) ----
#pragma unroll
        for (int i = 0; i < 4; i++) {
            int pos = i*256 + tid;        // 1024 segs
            int row = pos >> 4;
            int seg = pos & 15;
            *(uint4*)(Ks + row*QH + seg*8) =
                *(const uint4*)(kph + (size_t)(kb + row) * HD_ + seg*8);
        }
#pragma unroll
        for (int i = 0; i < 32; i++) {
            int pos = i*256 + tid;        // 8192 scalars
            int key = pos >> 7, hd = pos & 127;
            VT[hd*VH + key] = vph[(size_t)(kb + key) * HD_ + hd];
        }
        __syncthreads();

        // ---- QK^T ----
        float sc[8][4];
#pragma unroll
        for (int f = 0; f < 8; f++)
#pragma unroll
            for (int e = 0; e < 4; e++) sc[f][e] = 0.f;

#pragma unroll
        for (int kc = 0; kc < 8; kc++) {
            unsigned a0, a1, a2, a3;
            LDSM4(a0, a1, a2, a3, aq_base + (unsigned)(kc*32));
#pragma unroll
            for (int p = 0; p < 4; p++) {
                unsigned b0, b1, b2, b3;
                LDSM4(b0, b1, b2, b3,
                      ks_lane + (unsigned)(p*16*QH*2 + kc*32));
                MMAF16(sc[2*p],   a0, a1, a2, a3, b0, b1);
                MMAF16(sc[2*p+1], a0, a1, a2, a3, b2, b3);
            }
        }

        // ---- online softmax ----
        const bool maskt = (kb + 63 > q0);
        float mx0 = -INFINITY, mx1 = -INFINITY;
#pragma unroll
        for (int f = 0; f < 8; f++) {
            int cg = kb + f*8 + q_*2;
            float v0 = sc[f][0]*SCALE_, v1 = sc[f][1]*SCALE_;
            float v2 = sc[f][2]*SCALE_, v3 = sc[f][3]*SCALE_;
            if (maskt) {
                if (cg     > r0g)     v0 = -INFINITY;
                if (cg + 1 > r0g)     v1 = -INFINITY;
                if (cg     > r0g + 8) v2 = -INFINITY;
                if (cg + 1 > r0g + 8) v3 = -INFINITY;
            }
            sc[f][0] = v0; sc[f][1] = v1; sc[f][2] = v2; sc[f][3] = v3;
            mx0 = fmaxf(mx0, fmaxf(v0, v1));
            mx1 = fmaxf(mx1, fmaxf(v2, v3));
        }
        mx0 = fmaxf(mx0, __shfl_xor_sync(0xffffffffu, mx0, 1));
        mx0 = fmaxf(mx0, __shfl_xor_sync(0xffffffffu, mx0, 2));
        mx1 = fmaxf(mx1, __shfl_xor_sync(0xffffffffu, mx1, 1));
        mx1 = fmaxf(mx1, __shfl_xor_sync(0xffffffffu, mx1, 2));

        float mn0 = fmaxf(m0, mx0), mn1 = fmaxf(m1, mx1);
        float cr0 = 1.f, cr1 = 1.f;
        if ((mn0 > m0) || (mn1 > m1)) {
            cr0 = __expf(m0 - mn0);
            cr1 = __expf(m1 - mn1);
#pragma unroll
            for (int f = 0; f < 16; f++) {
                o[f][0] *= cr0; o[f][1] *= cr0;
                o[f][2] *= cr1; o[f][3] *= cr1;
            }
        }
        m0 = mn0; m1 = mn1;
        float s0 = 0.f, s1 = 0.f;
#pragma unroll
        for (int f = 0; f < 8; f++) {
            float p0 = __expf(sc[f][0] - mn0);
            float p1 = __expf(sc[f][1] - mn0);
            float p2 = __expf(sc[f][2] - mn1);
            float p3 = __expf(sc[f][3] - mn1);
            sc[f][0] = p0; sc[f][1] = p1; sc[f][2] = p2; sc[f][3] = p3;
            s0 += p0 + p1; s1 += p2 + p3;
        }
        l0 = l0*cr0 + s0; l1 = l1*cr1 + s1;

        // ---- P @ V ----
#pragma unroll
        for (int kc = 0; kc < 4; kc++) {
            unsigned pa0 = h2pack(sc[2*kc][0],   sc[2*kc][1]);
            unsigned pa1 = h2pack(sc[2*kc][2],   sc[2*kc][3]);
            unsigned pa2 = h2pack(sc[2*kc+1][0], sc[2*kc+1][1]);
            unsigned pa3 = h2pack(sc[2*kc+1][2], sc[2*kc+1][3]);
#pragma unroll
            for (int g = 0; g < 8; g++) {
                unsigned v0, v1, v2, v3;
                LDSM4(v0, v1, v2, v3,
                      vt_lane + (unsigned)(g*16*VH*2 + kc*32));
                MMAF16(o[2*g],   pa0, pa1, pa2, pa3, v0, v1);
                MMAF16(o[2*g+1], pa0, pa1, pa2, pa3, v2, v3);
            }
        }
    }

    // ---- normalize & write fp16 [B,S,H*HD] ----
    l0 += __shfl_xor_sync(0xffffffffu, l0, 1);
    l0 += __shfl_xor_sync(0xffffffffu, l0, 2);
    l1 += __shfl_xor_sync(0xffffffffu, l1, 1);
    l1 += __shfl_xor_sync(0xffffffffu, l1, 2);
    float inv0 = 1.f / l0, inv1 = 1.f / l1;

    const int b = bh >> 4, h = bh & 15;
    const int row0 = q0 + wid*16 + a_;
    __half* op0 = g_aoh + ((size_t)(b*S_ + row0))     * D_ + h*HD_;
    __half* op1 = g_aoh + ((size_t)(b*S_ + row0 + 8)) * D_ + h*HD_;
#pragma unroll
    for (int f = 0; f < 16; f++) {
        int c = f*8 + q_*2;
        *(unsigned*)(op0 + c) = h2pack(o[f][0]*inv0, o[f][1]*inv0);
        *(unsigned*)(op1 + c) = h2pack(o[f][2]*inv1, o[f][3]*inv1);
    }
}

// =====================================================================
extern "C" void kernel_launch(void* const* d_in, const int* in_sizes, int n_in,
                              void* d_out, int out_size)
{
    (void)in_sizes; (void)n_in; (void)out_size;
    const float* x    = (const float*)d_in[0];
    // d_in[1] = mask: exactly causal, implemented analytically
    const float* cosT = (const float*)d_in[2];
    const float* sinT = (const float*)d_in[3];
    const float* Wq   = (const float*)d_in[4];
    const float* Wk   = (const float*)d_in[5];
    const float* Wv   = (const float*)d_in[6];
    const float* Wo   = (const float*)d_in[7];
    float* out = (float*)d_out;

    cudaFuncSetAttribute(gemm_h,
        cudaFuncAttributeMaxDynamicSharedMemorySize, GS);
    cudaFuncSetAttribute(attn_h,
        cudaFuncAttributeMaxDynamicSharedMemorySize, ATT3_SMEM);

    // 0) fused fp32 -> fp16 conversion (x + 4 weights, one launch)
    f2h_all<<<12288, 256>>>(x, Wq, Wk, Wv, Wo);

    // 1) fused QKV projection -> fp16 [B,H,S,HD]
    dim3 gqkv(D_/TN, M_/TM, 3);
    gemm_h<<<gqkv, 256, GS>>>(nullptr, 0);

    // 2) RoPE in place on q,k (fp16)
    rope_h<<<(B_*H_*S_*16)/256, 256>>>(cosT, sinT);

    // 3) causal flash attention -> fp16 g_aoh [B,S,D]
    dim3 gatt(S_/128, B_*H_);
    attn_h<<<gatt, 256, ATT3_SMEM>>>();

    // 4) output projection -> fp32 d_out
    dim3 go(D_/TN, M_/TM, 1);
    gemm_h<<<go, 256, GS>>>(out, 1);
}

// round 17
// speedup vs baseline: 1.0502x; 1.0502x over previous
#include <cuda_runtime.h>
#include <cuda_fp16.h>
#include <math.h>

#define B_  2
#define S_  2048
#define D_  2048
#define H_  16
#define HD_ 128
#define M_  (B_*S_)          // 4096

#define SCALE_ 0.08838834764831845f   // 1/sqrt(128)

// -------- scratch (fp16, 16B-aligned via uint4 backing) --------
static __device__ uint4 g_qh_raw [B_*H_*S_*HD_/8];
static __device__ uint4 g_kh_raw [B_*H_*S_*HD_/8];
static __device__ uint4 g_vh_raw [B_*H_*S_*HD_/8];
static __device__ uint4 g_aoh_raw[B_*S_*D_/8];
static __device__ uint4 g_xh_raw [B_*S_*D_/8];
static __device__ uint4 g_wq_raw [D_*D_/8];
static __device__ uint4 g_wk_raw [D_*D_/8];
static __device__ uint4 g_wv_raw [D_*D_/8];
static __device__ uint4 g_wo_raw [D_*D_/8];
// device-side accessors ONLY (never touch these from host code!)
#define g_qh  ((__half*)g_qh_raw)
#define g_kh  ((__half*)g_kh_raw)
#define g_vh  ((__half*)g_vh_raw)
#define g_aoh ((__half*)g_aoh_raw)
#define g_xh  ((__half*)g_xh_raw)
#define g_wq  ((__half*)g_wq_raw)
#define g_wk  ((__half*)g_wk_raw)
#define g_wv  ((__half*)g_wv_raw)
#define g_wo  ((__half*)g_wo_raw)

// ===================== helpers =========================
__device__ __forceinline__ unsigned smem_u32(const void* p) {
    unsigned a;
    asm("{ .reg .u64 t; cvta.to.shared.u64 t, %1; cvt.u32.u64 %0, t; }"
        : "=r"(a) : "l"(p));
    return a;
}

#define LDSM4(r0,r1,r2,r3,a) \
    asm volatile("ldmatrix.sync.aligned.m8n8.x4.shared.b16 {%0,%1,%2,%3}, [%4];" \
        : "=r"(r0),"=r"(r1),"=r"(r2),"=r"(r3) : "r"(a))

#define MMAF16(d, a0,a1,a2,a3, b0,b1) \
    asm volatile("mma.sync.aligned.m16n8k16.row.col.f32.f16.f16.f32 " \
        "{%0,%1,%2,%3}, {%4,%5,%6,%7}, {%8,%9}, {%0,%1,%2,%3};" \
        : "+f"((d)[0]),"+f"((d)[1]),"+f"((d)[2]),"+f"((d)[3]) \
        : "r"(a0),"r"(a1),"r"(a2),"r"(a3),"r"(b0),"r"(b1))

#define CP16(dst, src) \
    asm volatile("cp.async.cg.shared.global [%0], [%1], 16;" \
                 :: "r"(dst), "l"(src) : "memory")
#define CP_COMMIT() asm volatile("cp.async.commit_group;" ::: "memory")
#define CP_WAIT0()  asm volatile("cp.async.wait_group 0;"  ::: "memory")
#define CP_WAIT1()  asm volatile("cp.async.wait_group 1;"  ::: "memory")

// pack two fp32 -> half2 (lo = first arg)
__device__ __forceinline__ unsigned h2pack(float lo, float hi) {
    unsigned r;
    asm("cvt.rn.f16x2.f32 %0, %1, %2;" : "=r"(r) : "f"(hi), "f"(lo));
    return r;
}
__device__ __forceinline__ float2 h2unpack(unsigned u) {
    __half2 h = *(__half2*)&u;
    return __half22float2(h);
}

// =====================================================================
// Single fused fp32 -> fp16 convert for x + 4 weights.
// Flat grid: blocks [0,4096): x ; [4096,12288): weights (2048 each).
// =====================================================================
__global__ void f2h_all(const float* __restrict__ x,
                        const float* __restrict__ wq,
                        const float* __restrict__ wk,
                        const float* __restrict__ wv,
                        const float* __restrict__ wo)
{
    int b = blockIdx.x;
    const float* src;
    __half* dst;
    int off;
    if (b < 4096) {
        src = x; dst = g_xh; off = b;
    } else {
        int w = (b - 4096) >> 11;        // 0..3
        off = (b - 4096) & 2047;
        src = (w == 0) ? wq : (w == 1) ? wk : (w == 2) ? wv : wo;
        dst = (w == 0) ? g_wq : (w == 1) ? g_wk : (w == 2) ? g_wv : g_wo;
    }
    int i = off * 2048 + threadIdx.x * 8;
    float4 a = *(const float4*)(src + i);
    float4 c = *(const float4*)(src + i + 4);
    uint4 r;
    r.x = h2pack(a.x, a.y); r.y = h2pack(a.z, a.w);
    r.z = h2pack(c.x, c.y); r.w = h2pack(c.z, c.w);
    *(uint4*)(dst + i) = r;
}

// =====================================================================
// fp16 NT GEMM (fp32 accum): C[m,n] = sum_k A[m,k] * W[n,k].
// CTA tile 128x128, warp tile 32x64 (4x2 grid), BK=32, 256 threads,
// cp.async.cg 16B staging, 3-stage pipeline (61.4KB), 2 CTA/SM.
// mode=0 (QKV): A=g_xh, W per blockIdx.z, scatter fp16 [B,H,S,HD]
// mode=1 (out): A=g_aoh, W=g_wo, write fp32 row-major to Cout
// =====================================================================
#define TM 128
#define TN 128
#define BKH 32
#define GNCH (D_/BKH)         // 64
#define HRS 40                // halves per row (80B; 16B-aligned rows)
#define ASZ (TM*HRS*2)        // 10240 B
#define BSZ (TN*HRS*2)        // 10240 B
#define BUF (ASZ+BSZ)         // 20480
#define NSTG 3
#define GS  (NSTG*BUF)        // 61440

__global__ __launch_bounds__(256, 2) void gemm_h(float* __restrict__ Cout, int mode)
{
    extern __shared__ char sm_[];
    const unsigned sbase = smem_u32(sm_);

    const int tid = threadIdx.x;
    const int wid = tid >> 5, lid = tid & 31;
    const int m0 = blockIdx.y * TM;
    const int n0 = blockIdx.x * TN;

    const __half* A;
    const __half* W;
    __half* outh = nullptr;
    if (mode == 0) {
        A = g_xh;
        W    = (blockIdx.z == 0) ? g_wq : (blockIdx.z == 1) ? g_wk : g_wv;
        outh = (blockIdx.z == 0) ? g_qh : (blockIdx.z == 1) ? g_kh : g_vh;
    } else {
        A = g_aoh;
        W = g_wo;
    }

    const int wm = wid >> 1, wn = wid & 1;   // warp tile rows wm*32, cols wn*64

    const unsigned aoff0 = (unsigned)(((wm*32 + (lid & 7) + ((lid & 8) ? 8 : 0)) * HRS
                                       + ((lid & 16) ? 8 : 0)) * 2);
    const unsigned boff0 = (unsigned)(((wn*64 + (lid & 7) + ((lid & 16) ? 8 : 0)) * HRS
                                       + ((lid & 8) ? 8 : 0)) * 2);

    // cp.async staging: rows tid>>2 and +64, 16B seg tid&3 (seg*8 halves)
    const int srow = tid >> 2, sseg = tid & 3;

    float acc[2][8][4];
#pragma unroll
    for (int mt = 0; mt < 2; mt++)
#pragma unroll
        for (int nt = 0; nt < 8; nt++)
#pragma unroll
            for (int e = 0; e < 4; e++) acc[mt][nt][e] = 0.f;

    // ---- prologue: async-load chunks 0 and 1 ----
#pragma unroll
    for (int pc = 0; pc < 2; pc++) {
        unsigned d = sbase + (unsigned)pc * BUF;
        int k0 = pc * BKH;
#pragma unroll
        for (int i = 0; i < 2; i++) {
            int r = srow + i*64;
            CP16(d + (unsigned)((r*HRS + sseg*8)*2),
                 A + (size_t)(m0 + r) * D_ + k0 + sseg*8);
            CP16(d + ASZ + (unsigned)((r*HRS + sseg*8)*2),
                 W + (size_t)(n0 + r) * D_ + k0 + sseg*8);
        }
        CP_COMMIT();
    }
    CP_WAIT1();       // chunk 0 resident
    __syncthreads();

#pragma unroll 1
    for (int c = 0; c < GNCH; c++) {
        // issue async copies for chunk c+2 (keep 2 chunks in flight)
        const int ci2 = c + 2;
        if (ci2 < GNCH) {
            unsigned d = sbase + (unsigned)(ci2 % NSTG) * BUF;
            int k0 = ci2 * BKH;
#pragma unroll
            for (int i = 0; i < 2; i++) {
                int r = srow + i*64;
                CP16(d + (unsigned)((r*HRS + sseg*8)*2),
                     A + (size_t)(m0 + r) * D_ + k0 + sseg*8);
                CP16(d + ASZ + (unsigned)((r*HRS + sseg*8)*2),
                     W + (size_t)(n0 + r) * D_ + k0 + sseg*8);
            }
            CP_COMMIT();
        }

        // ---- MMA over chunk c: 2 k16-steps ----
        const unsigned sA = sbase + (unsigned)(c % NSTG) * BUF;
        const unsigned sB = sA + ASZ;
#pragma unroll
        for (int ks = 0; ks < 2; ks++) {
            const unsigned kso = (unsigned)(ks * 32);   // 16 halves
            unsigned a0[2], a1[2], a2[2], a3[2];
#pragma unroll
            for (int mt = 0; mt < 2; mt++)
                LDSM4(a0[mt], a1[mt], a2[mt], a3[mt],
                      sA + aoff0 + (unsigned)(mt*16*HRS*2) + kso);
#pragma unroll
            for (int p = 0; p < 4; p++) {
                unsigned b0, b1, b2, b3;
                LDSM4(b0, b1, b2, b3,
                      sB + boff0 + (unsigned)(p*16*HRS*2) + kso);
#pragma unroll
                for (int mt = 0; mt < 2; mt++) {
                    MMAF16(acc[mt][2*p],   a0[mt], a1[mt], a2[mt], a3[mt], b0, b1);
                    MMAF16(acc[mt][2*p+1], a0[mt], a1[mt], a2[mt], a3[mt], b2, b3);
                }
            }
        }

        // ensure chunk c+1 is resident before next iteration
        if (ci2 < GNCH)            CP_WAIT1();
        else if (c + 1 < GNCH)     CP_WAIT0();
        __syncthreads();
    }

    // ---- epilogue (c-frag: rows lid>>2 / +8, cols (lid&3)*2) ----
#pragma unroll
    for (int mt = 0; mt < 2; mt++)
#pragma unroll
    for (int nt = 0; nt < 8; nt++) {
        int r  = m0 + wm*32 + mt*16 + (lid >> 2);
        int cc = n0 + wn*64 + nt*8 + (lid & 3)*2;
        if (mode != 0) {
            *(float2*)(Cout + (size_t)r * D_ + cc) =
                make_float2(acc[mt][nt][0], acc[mt][nt][1]);
            *(float2*)(Cout + (size_t)(r + 8) * D_ + cc) =
                make_float2(acc[mt][nt][2], acc[mt][nt][3]);
        } else {
            int h = cc >> 7, cd = cc & 127;
            int b1 = r >> 11, s1 = r & (S_ - 1);
            *(unsigned*)(outh + ((size_t)(b1*H_ + h) * S_ + s1) * HD_ + cd) =
                h2pack(acc[mt][nt][0], acc[mt][nt][1]);
            int r2 = r + 8;
            int b2 = r2 >> 11, s2 = r2 & (S_ - 1);
            *(unsigned*)(outh + ((size_t)(b2*H_ + h) * S_ + s2) * HD_ + cd) =
                h2pack(acc[mt][nt][2], acc[mt][nt][3]);
        }
    }
}

// =====================================================================
// RoPE in-place on fp16 g_qh, g_kh (compute fp32, 4 d-values / thread).
// =====================================================================
__global__ void rope_h(const float* __restrict__ cosT,
                       const float* __restrict__ sinT)
{
    int idx = blockIdx.x * blockDim.x + threadIdx.x;   // over B*H*S*16
    int d4 = (idx & 15) << 2;
    int s  = (idx >> 4) & (S_ - 1);
    int bh = idx >> 15;
    size_t base = ((size_t)bh * S_ + s) * HD_;
    float4 c  = *(const float4*)&cosT[s*HD_ + d4];
    float4 sn = *(const float4*)&sinT[s*HD_ + d4];

    uint2 q1u = *(uint2*)(g_qh + base + d4);
    uint2 q2u = *(uint2*)(g_qh + base + d4 + 64);
    float2 q1a = h2unpack(q1u.x), q1b = h2unpack(q1u.y);
    float2 q2a = h2unpack(q2u.x), q2b = h2unpack(q2u.y);
    uint2 o1, o2;
    o1.x = h2pack(q1a.x*c.x - q2a.x*sn.x, q1a.y*c.y - q2a.y*sn.y);
    o1.y = h2pack(q1b.x*c.z - q2b.x*sn.z, q1b.y*c.w - q2b.y*sn.w);
    o2.x = h2pack(q2a.x*c.x + q1a.x*sn.x, q2a.y*c.y + q1a.y*sn.y);
    o2.y = h2pack(q2b.x*c.z + q1b.x*sn.z, q2b.y*c.w + q1b.y*sn.w);
    *(uint2*)(g_qh + base + d4)      = o1;
    *(uint2*)(g_qh + base + d4 + 64) = o2;

    uint2 k1u = *(uint2*)(g_kh + base + d4);
    uint2 k2u = *(uint2*)(g_kh + base + d4 + 64);
    float2 k1a = h2unpack(k1u.x), k1b = h2unpack(k1u.y);
    float2 k2a = h2unpack(k2u.x), k2b = h2unpack(k2u.y);
    o1.x = h2pack(k1a.x*c.x - k2a.x*sn.x, k1a.y*c.y - k2a.y*sn.y);
    o1.y = h2pack(k1b.x*c.z - k2b.x*sn.z, k1b.y*c.w - k2b.y*sn.w);
    o2.x = h2pack(k2a.x*c.x + k1a.x*sn.x, k2a.y*c.y + k1a.y*sn.y);
    o2.y = h2pack(k2b.x*c.z + k1b.x*sn.z, k2b.y*c.w + k1b.y*sn.w);
    *(uint2*)(g_kh + base + d4)      = o1;
    *(uint2*)(g_kh + base + d4 + 64) = o2;
}

// =====================================================================
// Flash attention on fp16 tensor cores (fp32 accum). BQ=128, BK=64,
// 8 warps, P in registers, 1 CTA/SM (register-bound; 2 CTA/SM spills).
// Rescale skip kept (bit-identical).
// =====================================================================
#define QH 136
#define VH 72
#define KS_OFFH (128*QH)
#define VT_OFFH (KS_OFFH + 64*QH)
#define ATT3_SMEM ((VT_OFFH + 128*VH) * 2)   // 70656 bytes

__global__ __launch_bounds__(256, 1) void attn_h()
{
    extern __shared__ __half hsm[];
    __half* Qs = hsm;
    __half* Ks = hsm + KS_OFFH;
    __half* VT = hsm + VT_OFFH;

    const int tid = threadIdx.x;
    const int wid = tid >> 5, lid = tid & 31;
    const int qb  = 15 - (int)blockIdx.x;
    const int bh  = blockIdx.y;
    const int q0  = qb * 128;

    const __half* qph = g_qh + (size_t)bh * S_ * HD_;
    const __half* kph = g_kh + (size_t)bh * S_ * HD_;
    const __half* vph = g_vh + (size_t)bh * S_ * HD_;

    // ---- load Q tile (direct fp16 copy, 16B segs) ----
#pragma unroll
    for (int i = 0; i < 8; i++) {
        int pos = i*256 + tid;            // 2048 segs
        int row = pos >> 4;
        int seg = pos & 15;
        *(uint4*)(Qs + row*QH + seg*8) =
            *(const uint4*)(qph + (size_t)(q0 + row) * HD_ + seg*8);
    }

    const int a_ = lid >> 2, q_ = lid & 3;
    const int r0g = q0 + wid*16 + a_;

    const unsigned aq_base = smem_u32(Qs) +
        (unsigned)(((wid*16 + (lid & 7) + ((lid & 8) ? 8 : 0)) * QH
                    + ((lid & 16) ? 8 : 0)) * 2);
    const unsigned ks_lane = smem_u32(Ks) +
        (unsigned)((((lid & 7) + ((lid & 16) ? 8 : 0)) * QH
                    + ((lid & 8) ? 8 : 0)) * 2);
    const unsigned vt_lane = smem_u32(VT) +
        (unsigned)((((lid & 7) + ((lid & 16) ? 8 : 0)) * VH
                    + ((lid & 8) ? 8 : 0)) * 2);

    float m0 = -INFINITY, m1 = -INFINITY, l0 = 0.f, l1 = 0.f;
    float o[16][4];
#pragma unroll
    for (int f = 0; f < 16; f++)
#pragma unroll
        for (int e = 0; e < 4; e++) o[f][e] = 0.f;

    const int nt = 2*qb + 2;
#pragma unroll 1
    for (int t = 0; t < nt; t++) {
        const int kb = t * 64;
        __syncthreads();
        // ---- stage K (row-major) and V (transposed) ----
#pragma unroll
        for (int i = 0; i < 4; i++) {
            int pos = i*256 + tid;        // 1024 segs
            int row = pos >> 4;
            int seg = pos & 15;
            *(uint4*)(Ks + row*QH + seg*8) =
                *(const uint4*)(kph + (size_t)(kb + row) * HD_ + seg*8);
        }
#pragma unroll
        for (int i = 0; i < 32; i++) {
            int pos = i*256 + tid;        // 8192 scalars
            int key = pos >> 7, hd = pos & 127;
            VT[hd*VH + key] = vph[(size_t)(kb + key) * HD_ + hd];
        }
        __syncthreads();

        // ---- QK^T ----
        float sc[8][4];
#pragma unroll
        for (int f = 0; f < 8; f++)
#pragma unroll
            for (int e = 0; e < 4; e++) sc[f][e] = 0.f;

#pragma unroll
        for (int kc = 0; kc < 8; kc++) {
            unsigned a0, a1, a2, a3;
            LDSM4(a0, a1, a2, a3, aq_base + (unsigned)(kc*32));
#pragma unroll
            for (int p = 0; p < 4; p++) {
                unsigned b0, b1, b2, b3;
                LDSM4(b0, b1, b2, b3,
                      ks_lane + (unsigned)(p*16*QH*2 + kc*32));
                MMAF16(sc[2*p],   a0, a1, a2, a3, b0, b1);
                MMAF16(sc[2*p+1], a0, a1, a2, a3, b2, b3);
            }
        }

        // ---- online softmax ----
        const bool maskt = (kb + 63 > q0);
        float mx0 = -INFINITY, mx1 = -INFINITY;
#pragma unroll
        for (int f = 0; f < 8; f++) {
            int cg = kb + f*8 + q_*2;
            float v0 = sc[f][0]*SCALE_, v1 = sc[f][1]*SCALE_;
            float v2 = sc[f][2]*SCALE_, v3 = sc[f][3]*SCALE_;
            if (maskt) {
                if (cg     > r0g)     v0 = -INFINITY;
                if (cg + 1 > r0g)     v1 = -INFINITY;
                if (cg     > r0g + 8) v2 = -INFINITY;
                if (cg + 1 > r0g + 8) v3 = -INFINITY;
            }
            sc[f][0] = v0; sc[f][1] = v1; sc[f][2] = v2; sc[f][3] = v3;
            mx0 = fmaxf(mx0, fmaxf(v0, v1));
            mx1 = fmaxf(mx1, fmaxf(v2, v3));
        }
        mx0 = fmaxf(mx0, __shfl_xor_sync(0xffffffffu, mx0, 1));
        mx0 = fmaxf(mx0, __shfl_xor_sync(0xffffffffu, mx0, 2));
        mx1 = fmaxf(mx1, __shfl_xor_sync(0xffffffffu, mx1, 1));
        mx1 = fmaxf(mx1, __shfl_xor_sync(0xffffffffu, mx1, 2));

        float mn0 = fmaxf(m0, mx0), mn1 = fmaxf(m1, mx1);
        float cr0 = 1.f, cr1 = 1.f;
        if ((mn0 > m0) || (mn1 > m1)) {
            cr0 = __expf(m0 - mn0);
            cr1 = __expf(m1 - mn1);
#pragma unroll
            for (int f = 0; f < 16; f++) {
                o[f][0] *= cr0; o[f][1] *= cr0;
                o[f][2] *= cr1; o[f][3] *= cr1;
            }
        }
        m0 = mn0; m1 = mn1;
        float s0 = 0.f, s1 = 0.f;
#pragma unroll
        for (int f = 0; f < 8; f++) {
            float p0 = __expf(sc[f][0] - mn0);
            float p1 = __expf(sc[f][1] - mn0);
            float p2 = __expf(sc[f][2] - mn1);
            float p3 = __expf(sc[f][3] - mn1);
            sc[f][0] = p0; sc[f][1] = p1; sc[f][2] = p2; sc[f][3] = p3;
            s0 += p0 + p1; s1 += p2 + p3;
        }
        l0 = l0*cr0 + s0; l1 = l1*cr1 + s1;

        // ---- P @ V ----
#pragma unroll
        for (int kc = 0; kc < 4; kc++) {
            unsigned pa0 = h2pack(sc[2*kc][0],   sc[2*kc][1]);
            unsigned pa1 = h2pack(sc[2*kc][2],   sc[2*kc][3]);
            unsigned pa2 = h2pack(sc[2*kc+1][0], sc[2*kc+1][1]);
            unsigned pa3 = h2pack(sc[2*kc+1][2], sc[2*kc+1][3]);
#pragma unroll
            for (int g = 0; g < 8; g++) {
                unsigned v0, v1, v2, v3;
                LDSM4(v0, v1, v2, v3,
                      vt_lane + (unsigned)(g*16*VH*2 + kc*32));
                MMAF16(o[2*g],   pa0, pa1, pa2, pa3, v0, v1);
                MMAF16(o[2*g+1], pa0, pa1, pa2, pa3, v2, v3);
            }
        }
    }

    // ---- normalize & write fp16 [B,S,H*HD] ----
    l0 += __shfl_xor_sync(0xffffffffu, l0, 1);
    l0 += __shfl_xor_sync(0xffffffffu, l0, 2);
    l1 += __shfl_xor_sync(0xffffffffu, l1, 1);
    l1 += __shfl_xor_sync(0xffffffffu, l1, 2);
    float inv0 = 1.f / l0, inv1 = 1.f / l1;

    const int b = bh >> 4, h = bh & 15;
    const int row0 = q0 + wid*16 + a_;
    __half* op0 = g_aoh + ((size_t)(b*S_ + row0))     * D_ + h*HD_;
    __half* op1 = g_aoh + ((size_t)(b*S_ + row0 + 8)) * D_ + h*HD_;
#pragma unroll
    for (int f = 0; f < 16; f++) {
        int c = f*8 + q_*2;
        *(unsigned*)(op0 + c) = h2pack(o[f][0]*inv0, o[f][1]*inv0);
        *(unsigned*)(op1 + c) = h2pack(o[f][2]*inv1, o[f][3]*inv1);
    }
}

// =====================================================================
extern "C" void kernel_launch(void* const* d_in, const int* in_sizes, int n_in,
                              void* d_out, int out_size)
{
    (void)in_sizes; (void)n_in; (void)out_size;
    const float* x    = (const float*)d_in[0];
    // d_in[1] = mask: exactly causal, implemented analytically
    const float* cosT = (const float*)d_in[2];
    const float* sinT = (const float*)d_in[3];
    const float* Wq   = (const float*)d_in[4];
    const float* Wk   = (const float*)d_in[5];
    const float* Wv   = (const float*)d_in[6];
    const float* Wo   = (const float*)d_in[7];
    float* out = (float*)d_out;

    cudaFuncSetAttribute(gemm_h,
        cudaFuncAttributeMaxDynamicSharedMemorySize, GS);
    cudaFuncSetAttribute(attn_h,
        cudaFuncAttributeMaxDynamicSharedMemorySize, ATT3_SMEM);

    // 0) fused fp32 -> fp16 conversion (x + 4 weights, one launch)
    f2h_all<<<12288, 256>>>(x, Wq, Wk, Wv, Wo);

    // 1) fused QKV projection -> fp16 [B,H,S,HD]
    dim3 gqkv(D_/TN, M_/TM, 3);
    gemm_h<<<gqkv, 256, GS>>>(nullptr, 0);

    // 2) RoPE in place on q,k (fp16)
    rope_h<<<(B_*H_*S_*16)/256, 256>>>(cosT, sinT);

    // 3) causal flash attention -> fp16 g_aoh [B,S,D]
    dim3 gatt(S_/128, B_*H_);
    attn_h<<<gatt, 256, ATT3_SMEM>>>();

    // 4) output projection -> fp32 d_out
    dim3 go(D_/TN, M_/TM, 1);
    gemm_h<<<go, 256, GS>>>(out, 1);
}